// round 2
// baseline (speedup 1.0000x reference)
#include <cuda_runtime.h>

#define Bn 4
#define Cn 64
#define Hn 180
#define Wn 320
#define HW (Hn*Wn)            // 57600
#define CHW (Cn*HW)           // 3686400
#define BCHW (Bn*CHW)         // 14745600
#define BH (Bn*Hn)            // 720
#define WW (Wn*Wn)            // 102400
#define EPSV 1e-6f

// ---- scratch (allocation-free: static device globals) ----
__device__ float g_Ql[BCHW];
__device__ float g_Qr[BCHW];
__device__ float g_Vl[BCHW];
__device__ float g_Vr[BCHW];
__device__ float g_attn [BH*WW];   // [bh, w, v]
__device__ float g_attnT[BH*WW];   // [bh, v, w]

// ============================================================
// K1: per-pixel LayerNorm + Q/V 1x1-conv projections.
// LN is folded into effective weights so only xn lives in regs:
//   Q[co] = sum_ci (wq[co,ci]*lnw[ci]) * xn[ci] + (bq[co] + sum_ci wq[co,ci]*lnb[ci])
//   V[co] = sd * sum_ci wv[co,ci]*xn[ci] + mu * rowsum(wv[co,:]) + bv[co]
// ============================================================
__global__ __launch_bounds__(256) void k_proj(
    const float* __restrict__ x,
    const float* __restrict__ lnw, const float* __restrict__ lnb,
    const float* __restrict__ wq,  const float* __restrict__ bq,
    const float* __restrict__ wv,  const float* __restrict__ bv,
    int side)
{
    extern __shared__ float sm[];
    float* s_x  = sm;                 // 64*256
    float* s_wq = s_x + Cn*256;       // 4096
    float* s_wv = s_wq + Cn*Cn;       // 4096
    float* s_bq = s_wv + Cn*Cn;       // 64
    float* s_rs = s_bq + Cn;          // 64
    float* s_bv = s_rs + Cn;          // 64

    float* Qo = side ? g_Qr : g_Ql;
    float* Vo = side ? g_Vr : g_Vl;

    const int t    = threadIdx.x;
    const int pix0 = blockIdx.x * 256;
    const int b    = pix0 / HW;
    const int hw0  = pix0 - b*HW;
    const int base = b*CHW + hw0;

    for (int i = t; i < Cn*Cn; i += 256) {
        s_wq[i] = wq[i] * lnw[i & (Cn-1)];
        s_wv[i] = wv[i];
    }
    if (t < Cn) {
        float bb = bq[t], rs = 0.f;
        #pragma unroll
        for (int ci = 0; ci < Cn; ci++) {
            bb += wq[t*Cn+ci]*lnb[ci];
            rs += wv[t*Cn+ci];
        }
        s_bq[t] = bb; s_rs[t] = rs; s_bv[t] = bv[t];
    }
    #pragma unroll 8
    for (int c = 0; c < Cn; c++)
        s_x[c*256 + t] = x[base + c*HW + t];
    __syncthreads();

    float xn[Cn];
    float sum = 0.f, ss = 0.f;
    #pragma unroll
    for (int c = 0; c < Cn; c++) {
        float v = s_x[c*256 + t];
        xn[c] = v; sum += v; ss += v*v;
    }
    const float mu  = sum * (1.f/Cn);
    const float ve  = ss * (1.f/Cn) - mu*mu + EPSV;
    const float rsq = rsqrtf(ve);
    const float sd  = ve * rsq;               // sqrt(var+eps)
    #pragma unroll
    for (int c = 0; c < Cn; c++) xn[c] = (xn[c] - mu) * rsq;

    for (int co = 0; co < Cn; co++) {
        const float4* wq4 = reinterpret_cast<const float4*>(s_wq + co*Cn);
        const float4* wv4 = reinterpret_cast<const float4*>(s_wv + co*Cn);
        float aq = 0.f, av = 0.f;
        #pragma unroll
        for (int k = 0; k < Cn/4; k++) {
            float4 a = wq4[k], v4 = wv4[k];
            aq += a.x*xn[4*k] + a.y*xn[4*k+1] + a.z*xn[4*k+2] + a.w*xn[4*k+3];
            av += v4.x*xn[4*k] + v4.y*xn[4*k+1] + v4.z*xn[4*k+2] + v4.w*xn[4*k+3];
        }
        Qo[base + co*HW + t] = aq + s_bq[co];
        Vo[base + co*HW + t] = sd*av + mu*s_rs[co] + s_bv[co];
    }
}

// ============================================================
// K2: attn[bh,w,v] = scale * sum_c Ql[b,c,h,w]*Qr[b,c,h,v]
// Batched 320x320x64 GEMM; also writes the transposed copy so
// both softmax directions become row softmaxes.
// ============================================================
__global__ __launch_bounds__(256) void k_attn()
{
    __shared__ float s_a[Cn*64];
    __shared__ float s_b[Cn*64];
    const int t  = threadIdx.x;
    const int w0 = blockIdx.x*64, v0 = blockIdx.y*64;
    const int bh = blockIdx.z;
    const int b  = bh / Hn, h = bh - b*Hn;
    const int qbase = b*CHW + h*Wn;

    for (int i = t; i < Cn*64; i += 256) {
        int c = i >> 6, j = i & 63;
        s_a[i] = g_Ql[qbase + c*HW + w0 + j];
        s_b[i] = g_Qr[qbase + c*HW + v0 + j];
    }
    __syncthreads();

    const int tx = t & 15, ty = t >> 4;
    float acc[4][4] = {};
    #pragma unroll 4
    for (int c = 0; c < Cn; c++) {
        float4 a  = *reinterpret_cast<const float4*>(&s_a[c*64 + tx*4]);
        float4 bb = *reinterpret_cast<const float4*>(&s_b[c*64 + ty*4]);
        float av4[4] = {a.x, a.y, a.z, a.w};
        float bv4[4] = {bb.x, bb.y, bb.z, bb.w};
        #pragma unroll
        for (int iw = 0; iw < 4; iw++)
            #pragma unroll
            for (int iv = 0; iv < 4; iv++)
                acc[iw][iv] += av4[iw]*bv4[iv];
    }
    const float scale = 0.125f;  // C^-0.5
    const size_t abase = (size_t)bh * WW;
    #pragma unroll
    for (int iw = 0; iw < 4; iw++) {
        float4 r = make_float4(acc[iw][0]*scale, acc[iw][1]*scale,
                               acc[iw][2]*scale, acc[iw][3]*scale);
        *reinterpret_cast<float4*>(&g_attn[abase + (size_t)(w0+tx*4+iw)*Wn + v0+ty*4]) = r;
    }
    #pragma unroll
    for (int iv = 0; iv < 4; iv++) {
        float4 r = make_float4(acc[0][iv]*scale, acc[1][iv]*scale,
                               acc[2][iv]*scale, acc[3][iv]*scale);
        *reinterpret_cast<float4*>(&g_attnT[abase + (size_t)(v0+ty*4+iv)*Wn + w0+tx*4]) = r;
    }
}

// ============================================================
// K3/K4: row softmax of P[bh,r,:] then out[c,r] = x + coef[c]*sum_col P[r,col]*V[c,col]
// dir=0: P=attn,  V=V_r, out=out_l (rows are w)
// dir=1: P=attnT, V=V_l, out=out_r (rows are v)
// smem: sv transposed [320][65] (padded, conflict-free), sp [64][320], so [64][65].
// ============================================================
__global__ __launch_bounds__(256) void k_apply(
    int dir,
    const float* __restrict__ xin,
    const float* __restrict__ coef,
    float* __restrict__ out)
{
    extern __shared__ float sm[];
    float* sv = sm;              // 320*65
    float* sp = sv + Wn*65;      // 64*320
    float* so = sp + 64*Wn;      // 64*65

    const float* P = dir ? g_attnT : g_attn;
    const float* V = dir ? g_Vl   : g_Vr;

    const int t    = threadIdx.x;
    const int lane = t & 31, wrp = t >> 5;
    const int bh   = blockIdx.x;
    const int b    = bh / Hn, h = bh - b*Hn;
    const int vbase = b*CHW + h*Wn;
    const size_t pbase = (size_t)bh * WW;

    // load V transposed into padded smem
    for (int i = t; i < Cn*Wn; i += 256) {
        int c = i / Wn, v = i - c*Wn;
        sv[v*65 + c] = V[vbase + c*HW + v];
    }

    for (int r0 = 0; r0 < Wn; r0 += 64) {
        __syncthreads();   // sv ready (iter 0); prior consumers of sp/so done
        for (int i = t; i < 64*Wn; i += 256)
            sp[i] = P[pbase + (size_t)r0*Wn + i];
        __syncthreads();

        // softmax: warp wrp owns rows wrp*8 .. wrp*8+7 (it consumes them itself -> no sync after)
        for (int j = 0; j < 8; j++) {
            float* row = sp + (wrp*8 + j)*Wn;
            float e[10];
            float m = -1e30f;
            #pragma unroll
            for (int k = 0; k < 10; k++) { e[k] = row[lane + 32*k]; m = fmaxf(m, e[k]); }
            #pragma unroll
            for (int o = 16; o; o >>= 1) m = fmaxf(m, __shfl_xor_sync(0xffffffffu, m, o));
            float s = 0.f;
            #pragma unroll
            for (int k = 0; k < 10; k++) { e[k] = __expf(e[k] - m); s += e[k]; }
            #pragma unroll
            for (int o = 16; o; o >>= 1) s += __shfl_xor_sync(0xffffffffu, s, o);
            float inv = 1.f / s;
            #pragma unroll
            for (int k = 0; k < 10; k++) row[lane + 32*k] = e[k]*inv;
        }

        // P-rows x V^T: lane -> channels (lane, lane+32); 8 rows per warp
        float acc[8][2] = {};
        for (int v4 = 0; v4 < Wn; v4 += 4) {
            float f00 = sv[(v4+0)*65 + lane];
            float f01 = sv[(v4+1)*65 + lane];
            float f02 = sv[(v4+2)*65 + lane];
            float f03 = sv[(v4+3)*65 + lane];
            float f10 = sv[(v4+0)*65 + lane + 32];
            float f11 = sv[(v4+1)*65 + lane + 32];
            float f12 = sv[(v4+2)*65 + lane + 32];
            float f13 = sv[(v4+3)*65 + lane + 32];
            #pragma unroll
            for (int j = 0; j < 8; j++) {
                float4 p = *reinterpret_cast<const float4*>(&sp[(wrp*8+j)*Wn + v4]);
                acc[j][0] += p.x*f00 + p.y*f01 + p.z*f02 + p.w*f03;
                acc[j][1] += p.x*f10 + p.y*f11 + p.z*f12 + p.w*f13;
            }
        }
        #pragma unroll
        for (int j = 0; j < 8; j++) {
            int r = wrp*8 + j;
            so[lane*65 + r]      = acc[j][0];
            so[(lane+32)*65 + r] = acc[j][1];
        }
        __syncthreads();

        // residual + scale, coalesced global write
        for (int i = t; i < Cn*64; i += 256) {
            int c = i >> 6, r = i & 63;
            int g = vbase + c*HW + r0 + r;
            out[g] = xin[g] + coef[c]*so[c*65 + r];
        }
    }
}

// ============================================================
extern "C" void kernel_launch(void* const* d_in, const int* in_sizes, int n_in,
                              void* d_out, int out_size)
{
    const float* x_l   = (const float*)d_in[0];
    const float* x_r   = (const float*)d_in[1];
    const float* ln_l_w= (const float*)d_in[2];
    const float* ln_l_b= (const float*)d_in[3];
    const float* ln_r_w= (const float*)d_in[4];
    const float* ln_r_b= (const float*)d_in[5];
    const float* wq_l  = (const float*)d_in[6];
    const float* bq_l  = (const float*)d_in[7];
    const float* wq_r  = (const float*)d_in[8];
    const float* bq_r  = (const float*)d_in[9];
    const float* wv_l  = (const float*)d_in[10];
    const float* bv_l  = (const float*)d_in[11];
    const float* wv_r  = (const float*)d_in[12];
    const float* bv_r  = (const float*)d_in[13];
    const float* beta  = (const float*)d_in[14];
    const float* gamma = (const float*)d_in[15];
    float* out_l = (float*)d_out;
    float* out_r = out_l + BCHW;

    const int PROJ_SMEM  = (Cn*256 + 2*Cn*Cn + 3*Cn) * 4;   // 99072 B
    const int APPLY_SMEM = (Wn*65 + 64*Wn + Cn*65) * 4;     // 181760 B

    cudaFuncSetAttribute(k_proj,  cudaFuncAttributeMaxDynamicSharedMemorySize, PROJ_SMEM);
    cudaFuncSetAttribute(k_apply, cudaFuncAttributeMaxDynamicSharedMemorySize, APPLY_SMEM);

    k_proj<<<Bn*HW/256, 256, PROJ_SMEM>>>(x_l, ln_l_w, ln_l_b, wq_l, bq_l, wv_l, bv_l, 0);
    k_proj<<<Bn*HW/256, 256, PROJ_SMEM>>>(x_r, ln_r_w, ln_r_b, wq_r, bq_r, wv_r, bv_r, 1);
    k_attn<<<dim3(Wn/64, Wn/64, BH), 256>>>();
    k_apply<<<BH, 256, APPLY_SMEM>>>(0, x_l, beta,  out_l);
    k_apply<<<BH, 256, APPLY_SMEM>>>(1, x_r, gamma, out_r);
}

// round 3
// speedup vs baseline: 1.4843x; 1.4843x over previous
#include <cuda_runtime.h>

#define Bn 4
#define Cn 64
#define Hn 180
#define Wn 320
#define HW (Hn*Wn)            // 57600
#define CHW (Cn*HW)           // 3686400
#define BCHW (Bn*CHW)         // 14745600
#define BH (Bn*Hn)            // 720
#define WW (Wn*Wn)            // 102400
#define EPSV 1e-6f

// ---- scratch (allocation-free: static device globals) ----
__device__ float g_Ql[BCHW];
__device__ float g_Qr[BCHW];
__device__ float g_Vl[BCHW];
__device__ float g_Vr[BCHW];
__device__ float g_attn [BH*WW];   // [bh, w, v]
__device__ float g_attnT[BH*WW];   // [bh, v, w]

// ============================================================
// K1: per-pixel LayerNorm + Q/V 1x1-conv projections.
// ============================================================
__global__ __launch_bounds__(256) void k_proj(
    const float* __restrict__ x,
    const float* __restrict__ lnw, const float* __restrict__ lnb,
    const float* __restrict__ wq,  const float* __restrict__ bq,
    const float* __restrict__ wv,  const float* __restrict__ bv,
    int side)
{
    extern __shared__ float sm[];
    float* s_x  = sm;                 // 64*256
    float* s_wq = s_x + Cn*256;       // 4096
    float* s_wv = s_wq + Cn*Cn;       // 4096
    float* s_bq = s_wv + Cn*Cn;       // 64
    float* s_rs = s_bq + Cn;          // 64
    float* s_bv = s_rs + Cn;          // 64

    float* Qo = side ? g_Qr : g_Ql;
    float* Vo = side ? g_Vr : g_Vl;

    const int t    = threadIdx.x;
    const int pix0 = blockIdx.x * 256;
    const int b    = pix0 / HW;
    const int hw0  = pix0 - b*HW;
    const int base = b*CHW + hw0;

    for (int i = t; i < Cn*Cn; i += 256) {
        s_wq[i] = wq[i] * lnw[i & (Cn-1)];
        s_wv[i] = wv[i];
    }
    if (t < Cn) {
        float bb = bq[t], rs = 0.f;
        #pragma unroll
        for (int ci = 0; ci < Cn; ci++) {
            bb += wq[t*Cn+ci]*lnb[ci];
            rs += wv[t*Cn+ci];
        }
        s_bq[t] = bb; s_rs[t] = rs; s_bv[t] = bv[t];
    }
    #pragma unroll 8
    for (int c = 0; c < Cn; c++)
        s_x[c*256 + t] = x[base + c*HW + t];
    __syncthreads();

    float xn[Cn];
    float sum = 0.f, ss = 0.f;
    #pragma unroll
    for (int c = 0; c < Cn; c++) {
        float v = s_x[c*256 + t];
        xn[c] = v; sum += v; ss += v*v;
    }
    const float mu  = sum * (1.f/Cn);
    const float ve  = ss * (1.f/Cn) - mu*mu + EPSV;
    const float rsq = rsqrtf(ve);
    const float sd  = ve * rsq;               // sqrt(var+eps)
    #pragma unroll
    for (int c = 0; c < Cn; c++) xn[c] = (xn[c] - mu) * rsq;

    for (int co = 0; co < Cn; co++) {
        const float4* wq4 = reinterpret_cast<const float4*>(s_wq + co*Cn);
        const float4* wv4 = reinterpret_cast<const float4*>(s_wv + co*Cn);
        float aq = 0.f, av = 0.f;
        #pragma unroll
        for (int k = 0; k < Cn/4; k++) {
            float4 a = wq4[k], v4 = wv4[k];
            aq += a.x*xn[4*k] + a.y*xn[4*k+1] + a.z*xn[4*k+2] + a.w*xn[4*k+3];
            av += v4.x*xn[4*k] + v4.y*xn[4*k+1] + v4.z*xn[4*k+2] + v4.w*xn[4*k+3];
        }
        Qo[base + co*HW + t] = aq + s_bq[co];
        Vo[base + co*HW + t] = sd*av + mu*s_rs[co] + s_bv[co];
    }
}

// ============================================================
// K2: attn[bh,w,v] = scale * sum_c Ql[b,c,h,w]*Qr[b,c,h,v]
// Also writes the transposed copy so both softmax directions
// become row softmaxes.
// ============================================================
__global__ __launch_bounds__(256) void k_attn()
{
    __shared__ float s_a[Cn*64];
    __shared__ float s_b[Cn*64];
    const int t  = threadIdx.x;
    const int w0 = blockIdx.x*64, v0 = blockIdx.y*64;
    const int bh = blockIdx.z;
    const int b  = bh / Hn, h = bh - b*Hn;
    const int qbase = b*CHW + h*Wn;

    for (int i = t; i < Cn*64; i += 256) {
        int c = i >> 6, j = i & 63;
        s_a[i] = g_Ql[qbase + c*HW + w0 + j];
        s_b[i] = g_Qr[qbase + c*HW + v0 + j];
    }
    __syncthreads();

    const int tx = t & 15, ty = t >> 4;
    float acc[4][4] = {};
    #pragma unroll 4
    for (int c = 0; c < Cn; c++) {
        float4 a  = *reinterpret_cast<const float4*>(&s_a[c*64 + tx*4]);
        float4 bb = *reinterpret_cast<const float4*>(&s_b[c*64 + ty*4]);
        float av4[4] = {a.x, a.y, a.z, a.w};
        float bv4[4] = {bb.x, bb.y, bb.z, bb.w};
        #pragma unroll
        for (int iw = 0; iw < 4; iw++)
            #pragma unroll
            for (int iv = 0; iv < 4; iv++)
                acc[iw][iv] += av4[iw]*bv4[iv];
    }
    const float scale = 0.125f;  // C^-0.5
    const size_t abase = (size_t)bh * WW;
    #pragma unroll
    for (int iw = 0; iw < 4; iw++) {
        float4 r = make_float4(acc[iw][0]*scale, acc[iw][1]*scale,
                               acc[iw][2]*scale, acc[iw][3]*scale);
        *reinterpret_cast<float4*>(&g_attn[abase + (size_t)(w0+tx*4+iw)*Wn + v0+ty*4]) = r;
    }
    #pragma unroll
    for (int iv = 0; iv < 4; iv++) {
        float4 r = make_float4(acc[0][iv]*scale, acc[1][iv]*scale,
                               acc[2][iv]*scale, acc[3][iv]*scale);
        *reinterpret_cast<float4*>(&g_attnT[abase + (size_t)(v0+ty*4+iv)*Wn + w0+tx*4]) = r;
    }
}

// ============================================================
// K3/K4 (restructured for occupancy): one 32-row tile per block.
//   grid = (Wn/32, BH), 256 threads.
//   smem = sp[32][320] (P rows, 40KB) + svc[64][65] (V chunk, 16.6KB)
//        + so[64][33] (8.4KB)  => 64.5KB -> 3 CTAs/SM.
//   Row softmax (warp-owns-rows, no post-sync), then F = P x V^T
//   streaming V in 64-wide chunks with register prefetch.
// ============================================================
#define RT 32                       // rows per block
#define VC 64                       // v-chunk width

__global__ __launch_bounds__(256) void k_apply(
    int dir,
    const float* __restrict__ xin,
    const float* __restrict__ coef,
    float* __restrict__ out)
{
    extern __shared__ float sm[];
    float* sp  = sm;                  // RT*320
    float* svc = sp + RT*Wn;          // VC*65
    float* so  = svc + VC*65;         // 64*33

    const float* __restrict__ P = dir ? g_attnT : g_attn;
    const float* __restrict__ V = dir ? g_Vl   : g_Vr;

    const int t    = threadIdx.x;
    const int lane = t & 31, wrp = t >> 5;
    const int r0   = blockIdx.x * RT;
    const int bh   = blockIdx.y;
    const int b    = bh / Hn, h = bh - b*Hn;
    const int vbase = b*CHW + h*Wn;
    const size_t pbase = (size_t)bh * WW + (size_t)r0 * Wn;

    // ---- load P tile (coalesced) ----
    #pragma unroll
    for (int i = 0; i < RT*Wn/256; i++)
        sp[t + i*256] = P[pbase + t + i*256];
    __syncthreads();

    // ---- softmax: warp wrp owns rows wrp*4 .. wrp*4+3 ----
    #pragma unroll
    for (int j = 0; j < 4; j++) {
        float* row = sp + (wrp*4 + j)*Wn;
        float e[10];
        float m = -1e30f;
        #pragma unroll
        for (int k = 0; k < 10; k++) { e[k] = row[lane + 32*k]; m = fmaxf(m, e[k]); }
        #pragma unroll
        for (int o = 16; o; o >>= 1) m = fmaxf(m, __shfl_xor_sync(0xffffffffu, m, o));
        float s = 0.f;
        #pragma unroll
        for (int k = 0; k < 10; k++) { e[k] = __expf(e[k] - m); s += e[k]; }
        #pragma unroll
        for (int o = 16; o; o >>= 1) s += __shfl_xor_sync(0xffffffffu, s, o);
        float inv = 1.f / s;
        #pragma unroll
        for (int k = 0; k < 10; k++) row[lane + 32*k] = e[k]*inv;
    }
    // no sync: each warp consumes only its own sp rows below.

    // ---- F = P x V^T, streaming V in VC-wide chunks ----
    // prefetch slot mapping: s = t + q*256 ; c = s>>4 ; vv4 = (s&15)*4
    float4 pf[4];
    {
        #pragma unroll
        for (int q = 0; q < 4; q++) {
            int s = t + q*256;
            int c = s >> 4, vv4 = (s & 15) * 4;
            pf[q] = *reinterpret_cast<const float4*>(&V[vbase + c*HW + vv4]);
        }
    }

    float acc[4][2] = {};
    for (int cc = 0; cc < Wn/VC; cc++) {
        __syncthreads();   // previous chunk fully consumed
        #pragma unroll
        for (int q = 0; q < 4; q++) {
            int s = t + q*256;
            int c = s >> 4, vv4 = (s & 15) * 4;
            svc[(vv4+0)*65 + c] = pf[q].x;
            svc[(vv4+1)*65 + c] = pf[q].y;
            svc[(vv4+2)*65 + c] = pf[q].z;
            svc[(vv4+3)*65 + c] = pf[q].w;
        }
        __syncthreads();

        if (cc < Wn/VC - 1) {
            int v0n = (cc+1)*VC;
            #pragma unroll
            for (int q = 0; q < 4; q++) {
                int s = t + q*256;
                int c = s >> 4, vv4 = (s & 15) * 4;
                pf[q] = *reinterpret_cast<const float4*>(&V[vbase + c*HW + v0n + vv4]);
            }
        }

        const int pco = cc*VC;
        #pragma unroll 2
        for (int v4 = 0; v4 < VC; v4 += 4) {
            float f0[4], f1[4];
            #pragma unroll
            for (int k = 0; k < 4; k++) {
                f0[k] = svc[(v4+k)*65 + lane];
                f1[k] = svc[(v4+k)*65 + lane + 32];
            }
            #pragma unroll
            for (int j = 0; j < 4; j++) {
                float4 p = *reinterpret_cast<const float4*>(&sp[(wrp*4+j)*Wn + pco + v4]);
                acc[j][0] += p.x*f0[0] + p.y*f0[1] + p.z*f0[2] + p.w*f0[3];
                acc[j][1] += p.x*f1[0] + p.y*f1[1] + p.z*f1[2] + p.w*f1[3];
            }
        }
    }

    // ---- stage to smem (transpose), then coalesced residual write ----
    #pragma unroll
    for (int j = 0; j < 4; j++) {
        int r = wrp*4 + j;
        so[lane*33 + r]      = acc[j][0];
        so[(lane+32)*33 + r] = acc[j][1];
    }
    __syncthreads();

    #pragma unroll
    for (int i = 0; i < Cn*RT/256; i++) {
        int idx = t + i*256;
        int c = idx >> 5, r = idx & (RT-1);
        int g = vbase + c*HW + r0 + r;
        out[g] = xin[g] + coef[c]*so[c*33 + r];
    }
}

// ============================================================
extern "C" void kernel_launch(void* const* d_in, const int* in_sizes, int n_in,
                              void* d_out, int out_size)
{
    const float* x_l   = (const float*)d_in[0];
    const float* x_r   = (const float*)d_in[1];
    const float* ln_l_w= (const float*)d_in[2];
    const float* ln_l_b= (const float*)d_in[3];
    const float* ln_r_w= (const float*)d_in[4];
    const float* ln_r_b= (const float*)d_in[5];
    const float* wq_l  = (const float*)d_in[6];
    const float* bq_l  = (const float*)d_in[7];
    const float* wq_r  = (const float*)d_in[8];
    const float* bq_r  = (const float*)d_in[9];
    const float* wv_l  = (const float*)d_in[10];
    const float* bv_l  = (const float*)d_in[11];
    const float* wv_r  = (const float*)d_in[12];
    const float* bv_r  = (const float*)d_in[13];
    const float* beta  = (const float*)d_in[14];
    const float* gamma = (const float*)d_in[15];
    float* out_l = (float*)d_out;
    float* out_r = out_l + BCHW;

    const int PROJ_SMEM  = (Cn*256 + 2*Cn*Cn + 3*Cn) * 4;          // 99072 B
    const int APPLY_SMEM = (RT*Wn + VC*65 + Cn*33) * 4;            // 66048 B

    cudaFuncSetAttribute(k_proj,  cudaFuncAttributeMaxDynamicSharedMemorySize, PROJ_SMEM);
    cudaFuncSetAttribute(k_apply, cudaFuncAttributeMaxDynamicSharedMemorySize, APPLY_SMEM);

    k_proj<<<Bn*HW/256, 256, PROJ_SMEM>>>(x_l, ln_l_w, ln_l_b, wq_l, bq_l, wv_l, bv_l, 0);
    k_proj<<<Bn*HW/256, 256, PROJ_SMEM>>>(x_r, ln_r_w, ln_r_b, wq_r, bq_r, wv_r, bv_r, 1);
    k_attn<<<dim3(Wn/64, Wn/64, BH), 256>>>();
    k_apply<<<dim3(Wn/RT, BH), 256, APPLY_SMEM>>>(0, x_l, beta,  out_l);
    k_apply<<<dim3(Wn/RT, BH), 256, APPLY_SMEM>>>(1, x_r, gamma, out_r);
}